// round 16
// baseline (speedup 1.0000x reference)
#include <cuda_runtime.h>
#include <cuda_fp16.h>
#include <cstdint>
#include <math.h>

#define BATCH 16
#define PP    8192
#define NTOT  (BATCH*PP)     // 131072
#define KNN   4
#define CDIM  256
#define HEADS 4
#define FDIM  64
#define GRID  64
#define NCELL (GRID*GRID)    // 4096
#define NEG_SLOPE 0.2f

// ------------------- scratch (__device__ globals, no mallocs) -------------------
__device__ int      d_cnt[BATCH*NCELL];
__device__ int      d_start[BATCH*(NCELL+1)];
__device__ int      d_cur[BATCH*NCELL];
__device__ int      d_sorted[NTOT];
__device__ float2   d_sc[NTOT];
__device__ int      d_nbr[NTOT*KNN];
__device__ __half   d_hh[NTOT*CDIM];       // GEMM output (fp16, sorted space)
__device__ __half   d_ah[NTOT*CDIM];       // fp16 GEMM input
__device__ float    d_as[2*NTOT*HEADS];    // att scalars, per-layer halves
__device__ float    d_ad[2*NTOT*HEADS];
__device__ float    d_h2[NTOT*2];
__device__ float    d_a2s[NTOT];
__device__ float    d_a2d[NTOT];
__device__ uint32_t d_wp0[256*128];        // W packed k-major: [n][k2] half2
__device__ uint32_t d_wp1[256*128];

// ----------------------------- PTX helpers --------------------------------------
__device__ __forceinline__ uint32_t smem_u32(const void* p) {
    uint32_t a;
    asm("{ .reg .u64 t; cvta.to.shared.u64 t, %1; cvt.u32.u64 %0, t; }" : "=r"(a) : "l"(p));
    return a;
}
__device__ __forceinline__ void cp16(uint32_t dst, const void* src) {
    asm volatile("cp.async.cg.shared.global [%0], [%1], 16;" :: "r"(dst), "l"(src));
}
#define CP_COMMIT() asm volatile("cp.async.commit_group;" ::: "memory")
#define CP_WAIT(N)  asm volatile("cp.async.wait_group %0;" :: "n"(N) : "memory")

__device__ __forceinline__ void mma_f16(float d[4], const uint32_t a[4], const uint32_t b[2]) {
    asm volatile(
        "mma.sync.aligned.m16n8k16.row.col.f32.f16.f16.f32 "
        "{%0,%1,%2,%3}, {%4,%5,%6,%7}, {%8,%9}, {%0,%1,%2,%3};"
        : "+f"(d[0]), "+f"(d[1]), "+f"(d[2]), "+f"(d[3])
        : "r"(a[0]), "r"(a[1]), "r"(a[2]), "r"(a[3]), "r"(b[0]), "r"(b[1]));
}
__device__ __forceinline__ void ldsm_x4(uint32_t r[4], uint32_t addr) {
    asm volatile("ldmatrix.sync.aligned.m8n8.x4.shared.b16 {%0,%1,%2,%3}, [%4];"
        : "=r"(r[0]), "=r"(r[1]), "=r"(r[2]), "=r"(r[3]) : "r"(addr));
}

// -------------- prep: zero counters/att-scalars + pack both W (fused) ----------
__global__ void prep_kernel(const float* __restrict__ W0, const float* __restrict__ W1,
                            uint32_t* __restrict__ Wp0, uint32_t* __restrict__ Wp1) {
    int i = blockIdx.x * blockDim.x + threadIdx.x;
    if (i < BATCH*NCELL) d_cnt[i] = 0;
    if (i < 2*NTOT*HEADS) { d_as[i] = 0.f; d_ad[i] = 0.f; }
    if (i < 256*128) {
        int n = i >> 7, k2 = i & 127;
        __half2 v0 = __floats2half2_rn(W0[(2*k2)*CDIM + n], W0[(2*k2+1)*CDIM + n]);
        __half2 v1 = __floats2half2_rn(W1[(2*k2)*CDIM + n], W1[(2*k2+1)*CDIM + n]);
        Wp0[i] = *(uint32_t*)&v0;
        Wp1[i] = *(uint32_t*)&v1;
    }
}

// ------------------------------- kNN pipeline ----------------------------------
__device__ __forceinline__ int cell_of(float v) {
    int c = (int)(v * GRID);
    return min(GRID-1, max(0, c));
}
__global__ void count_kernel(const float* __restrict__ coords) {
    int i = blockIdx.x * blockDim.x + threadIdx.x;
    if (i >= NTOT) return;
    float2 c = ((const float2*)coords)[i];
    int b = i >> 13;
    atomicAdd(&d_cnt[b*NCELL + cell_of(c.y)*GRID + cell_of(c.x)], 1);
}
// NCELL=4096, 1024 threads: per-thread 4-cell sums + shuffle-based block scan.
__global__ void scan_kernel() {
    __shared__ int s[32];
    int b = blockIdx.x, t = threadIdx.x;
    int lane = t & 31, wrp = t >> 5;
    int base = b*NCELL + t*4;
    int v0 = d_cnt[base], v1 = d_cnt[base+1], v2 = d_cnt[base+2], v3 = d_cnt[base+3];
    int p0 = v0, p1 = p0 + v1, p2 = p1 + v2, p3 = p2 + v3;
    int w = p3;
    #pragma unroll
    for (int off = 1; off < 32; off <<= 1) {
        int n = __shfl_up_sync(0xffffffffu, w, off);
        if (lane >= off) w += n;
    }
    if (lane == 31) s[wrp] = w;
    __syncthreads();
    if (wrp == 0) {
        int v = s[lane];
        #pragma unroll
        for (int off = 1; off < 32; off <<= 1) {
            int n = __shfl_up_sync(0xffffffffu, v, off);
            if (lane >= off) v += n;
        }
        s[lane] = v;
    }
    __syncthreads();
    int warpbase = (wrp > 0) ? s[wrp-1] : 0;
    int incl = warpbase + w;
    int gbase = incl - p3;
    int o = b*(NCELL+1) + t*4;
    d_start[o]   = gbase;
    d_start[o+1] = gbase + p0;
    d_start[o+2] = gbase + p1;
    d_start[o+3] = gbase + p2;
    int c = b*NCELL + t*4;
    d_cur[c]   = gbase;
    d_cur[c+1] = gbase + p0;
    d_cur[c+2] = gbase + p1;
    d_cur[c+3] = gbase + p2;
    if (t == 1023) d_start[b*(NCELL+1) + NCELL] = incl;
}
__global__ void scatter_kernel(const float* __restrict__ coords) {
    int i = blockIdx.x * blockDim.x + threadIdx.x;
    if (i >= NTOT) return;
    float2 c = ((const float2*)coords)[i];
    int b = i >> 13, p = i & (PP-1);
    int cell = cell_of(c.y)*GRID + cell_of(c.x);
    int pos = atomicAdd(&d_cur[b*NCELL + cell], 1);
    d_sorted[b*PP + pos] = p;
    d_sc[b*PP + pos] = c;
}

__device__ __forceinline__ void ins4(float d2, int gi, float bd[4], int bi[4]) {
    if (d2 < bd[3]) {
        if (d2 < bd[2]) { bd[3]=bd[2]; bi[3]=bi[2];
            if (d2 < bd[1]) { bd[2]=bd[1]; bi[2]=bi[1];
                if (d2 < bd[0]) { bd[1]=bd[0]; bi[1]=bi[0]; bd[0]=d2; bi[0]=gi; }
                else            { bd[1]=d2; bi[1]=gi; }
            } else { bd[2]=d2; bi[2]=gi; }
        } else { bd[3]=d2; bi[3]=gi; }
    }
}
__device__ __forceinline__ void scan_cell(int b, int cell, float qx, float qy,
                                          float bd[4], int bi[4]) {
    int s0 = d_start[b*(NCELL+1) + cell];
    int s1 = d_start[b*(NCELL+1) + cell + 1];
    int base = b << 13;
    for (int j = s0; j < s1; j++) {
        float2 c2 = d_sc[base + j];
        float dx = c2.x - qx, dy = c2.y - qy;
        ins4(dx*dx + dy*dy, base + j, bd, bi);
    }
}

__device__ __forceinline__ void knn_work(int n) {
    int b = n >> 13;
    float2 q = d_sc[n];
    int cx = cell_of(q.x), cy = cell_of(q.y);
    float bd[4] = {1e30f, 1e30f, 1e30f, 1e30f};
    int   bi[4] = {n, n, n, n};
    int x0 = max(0, cx-1), x1 = min(GRID-1, cx+1);
    int y0 = max(0, cy-1), y1 = min(GRID-1, cy+1);
    for (int yy = y0; yy <= y1; yy++) {
        int s0 = d_start[b*(NCELL+1) + yy*GRID + x0];
        int s1 = d_start[b*(NCELL+1) + yy*GRID + x1 + 1];
        int base = b << 13;
        for (int j = s0; j < s1; j++) {
            float2 c2 = d_sc[base + j];
            float dx = c2.x - q.x, dy = c2.y - q.y;
            ins4(dx*dx + dy*dy, base + j, bd, bi);
        }
    }
    const float hcell = 1.0f / GRID;
    int r = 1;
    while (true) {
        float bound = r * hcell;
        if (bd[3] <= bound*bound) break;
        bool full = (cx-r <= 0) && (cy-r <= 0) && (cx+r >= GRID-1) && (cy+r >= GRID-1);
        if (full) break;
        r++;
        int rx0 = cx-r, rx1 = cx+r, ry0 = cy-r, ry1 = cy+r;
        int cxl = max(0, rx0), cxr = min(GRID-1, rx1);
        if (ry0 >= 0) {
            int s0 = d_start[b*(NCELL+1) + ry0*GRID + cxl];
            int s1 = d_start[b*(NCELL+1) + ry0*GRID + cxr + 1];
            int base = b << 13;
            for (int j = s0; j < s1; j++) {
                float2 c2 = d_sc[base + j];
                float dx = c2.x - q.x, dy = c2.y - q.y;
                ins4(dx*dx + dy*dy, base + j, bd, bi);
            }
        }
        if (ry1 <= GRID-1) {
            int s0 = d_start[b*(NCELL+1) + ry1*GRID + cxl];
            int s1 = d_start[b*(NCELL+1) + ry1*GRID + cxr + 1];
            int base = b << 13;
            for (int j = s0; j < s1; j++) {
                float2 c2 = d_sc[base + j];
                float dx = c2.x - q.x, dy = c2.y - q.y;
                ins4(dx*dx + dy*dy, base + j, bd, bi);
            }
        }
        int cyl = max(0, ry0+1), cyr = min(GRID-1, ry1-1);
        if (rx0 >= 0)      for (int yy = cyl; yy <= cyr; yy++) scan_cell(b, yy*GRID + rx0, q.x, q.y, bd, bi);
        if (rx1 <= GRID-1) for (int yy = cyl; yy <= cyr; yy++) scan_cell(b, yy*GRID + rx1, q.x, q.y, bd, bi);
    }
    #pragma unroll
    for (int k = 0; k < KNN; k++) d_nbr[n*KNN + k] = bi[k];
}

// -------- fused: blocks [0,512) do kNN; blocks [512, 512+16384) do permute -----
#define KNN_BLOCKS 512
#define PERM_BLOCKS (NTOT/8)

__global__ void knn_perm_kernel(const float* __restrict__ x, __half* __restrict__ xp) {
    if (blockIdx.x < KNN_BLOCKS) {
        int n = blockIdx.x * blockDim.x + threadIdx.x;
        if (n < NTOT) knn_work(n);
    } else {
        int w = ((blockIdx.x - KNN_BLOCKS) * blockDim.x + threadIdx.x) >> 5;
        int lane = threadIdx.x & 31;
        if (w >= NTOT) return;
        int orig = ((w >> 13) << 13) + d_sorted[w];
        const float4* src = (const float4*)(x + (size_t)orig*CDIM);
        float4 v0 = src[lane*2], v1 = src[lane*2 + 1];
        __half2 h0 = __floats2half2_rn(v0.x, v0.y);
        __half2 h1 = __floats2half2_rn(v0.z, v0.w);
        __half2 h2 = __floats2half2_rn(v1.x, v1.y);
        __half2 h3 = __floats2half2_rn(v1.z, v1.w);
        uint4 o;
        o.x = *(uint32_t*)&h0; o.y = *(uint32_t*)&h1;
        o.z = *(uint32_t*)&h2; o.w = *(uint32_t*)&h3;
        *(uint4*)(xp + (size_t)w*CDIM + lane*8) = o;
    }
}

// --------------- fp16 persistent-W GEMM + fused attention scalars --------------
// 4-deep A pipeline, ONE __syncthreads per chunk, ldmatrix for A AND B fragments.
#define NS2K 132                       // W smem row stride (u32): 128 k2 + 4 pad
#define AS2 20
#define W_SMEM_U32 (128*NS2K)          // 16896 u32 (128 n-rows per CTA half)
#define A_SMEM_H2 (128*AS2)            // 2560 u32
#define NBUF 4
#define GEMM_SMEM ((W_SMEM_U32 + NBUF*A_SMEM_H2)*4)   // 108544 bytes

__global__ void __launch_bounds__(256, 2) gemm_f16_kernel(
    const __half* __restrict__ A, const uint32_t* __restrict__ Wp,
    const float* __restrict__ asrc, const float* __restrict__ adst,
    __half* __restrict__ Hout, float* __restrict__ asb, float* __restrict__ adb)
{
    extern __shared__ uint32_t sm2[];
    uint32_t sbase = smem_u32(sm2);
    uint32_t abase = sbase + W_SMEM_U32*4;

    int tid = threadIdx.x;
    int wid = tid >> 5, lane = tid & 31;
    int g = lane >> 2, t = lane & 3;
    int wm = wid & 1, wn = wid >> 1;
    int cHalf = blockIdx.y;
    int colBase = cHalf*128;

    // stage W half (128 n-rows x 128 k2) into smem, k-major rows
    for (int i = tid; i < 128*32; i += 256) {
        int nl = i >> 5, k4 = i & 31;
        cp16(sbase + (uint32_t)(nl*NS2K + k4*4)*4, Wp + (size_t)(colBase + nl)*128 + k4*4);
    }
    CP_COMMIT();

    float sa0[4], sa1[4], sd0[4], sd1[4];
    #pragma unroll
    for (int nt = 0; nt < 4; nt++) {
        int col = colBase + wn*32 + nt*8 + t*2;
        sa0[nt] = asrc[col]; sa1[nt] = asrc[col+1];
        sd0[nt] = adst[col]; sd1[nt] = adst[col+1];
    }
    int hHead = (colBase + wn*32) >> 6;

    int ntiles = (1024 - blockIdx.x + 147) / 148;
    int nchunks = ntiles * 8;

    auto issue = [&](int c) {
        int rt = blockIdx.x + (c >> 3)*148;
        int kk = c & 7;
        const __half* src = A + (size_t)rt*128*CDIM + kk*32;
        uint32_t dstb = abase + (uint32_t)(c & (NBUF-1))*A_SMEM_H2*4;
        #pragma unroll
        for (int i = 0; i < 2; i++) {
            int idx = tid + i*256;
            int r = idx >> 2, c4 = idx & 3;
            cp16(dstb + (uint32_t)(r*AS2 + c4*4)*4, src + (size_t)r*CDIM + c4*8);
        }
        CP_COMMIT();
    };

    float acc[4][4][4];
    #pragma unroll
    for (int mt = 0; mt < 4; mt++)
        #pragma unroll
        for (int nt = 0; nt < 4; nt++)
            #pragma unroll
            for (int i = 0; i < 4; i++) acc[mt][nt][i] = 0.f;

    issue(0);
    if (nchunks > 1) issue(1);
    if (nchunks > 2) issue(2);

    // A ldmatrix per-lane offset (u32): lanes 0-15 rows 0-15 @k 0; 16-31 @ +4
    uint32_t lrowA = (uint32_t)((wm*64 + (lane & 15))*AS2 + (lane >> 4)*4);
    // B ldmatrix per-lane offsets (u32): 4 matrices = (nt, khalf) pairs
    int mi = lane >> 3, brow = lane & 7;
    int ntA = mi >> 1, khf = mi & 1;
    uint32_t lB0 = (uint32_t)((wn*32 + ntA*8     + brow)*NS2K + khf*4);   // nt 0,1
    uint32_t lB1 = (uint32_t)((wn*32 + (ntA+2)*8 + brow)*NS2K + khf*4);   // nt 2,3

    #pragma unroll 1
    for (int c = 0; c < nchunks; c++) {
        int d = nchunks - 1 - c;
        if (d >= 2)      { CP_WAIT(2); }
        else if (d == 1) { CP_WAIT(1); }
        else             { CP_WAIT(0); }
        __syncthreads();     // all warps done with chunk c-1; buffer (c+3)%4 free
        int kk = c & 7;
        uint32_t abuf_b = abase + (uint32_t)(c & (NBUF-1))*A_SMEM_H2*4;
        #pragma unroll
        for (int ks = 0; ks < 2; ks++) {
            int kh = ks*8;
            uint32_t koff = (uint32_t)(kk*16 + kh);
            uint32_t af[4][4], b01[4], b23[4];
            #pragma unroll
            for (int mt = 0; mt < 4; mt++)
                ldsm_x4(af[mt], abuf_b + (lrowA + (uint32_t)(mt*16*AS2 + kh))*4);
            ldsm_x4(b01, sbase + (lB0 + koff)*4);
            ldsm_x4(b23, sbase + (lB1 + koff)*4);
            #pragma unroll
            for (int mt = 0; mt < 4; mt++) {
                #pragma unroll
                for (int nt = 0; nt < 4; nt++) {
                    const uint32_t* bb = (nt < 2) ? &b01[nt*2] : &b23[(nt-2)*2];
                    mma_f16(acc[mt][nt], af[mt], bb);
                }
            }
        }
        if (kk == 7) {
            int rt = blockIdx.x + (c >> 3)*148;
            int rowBase = rt*128;
            #pragma unroll
            for (int mt = 0; mt < 4; mt++) {
                int r0 = rowBase + wm*64 + mt*16 + g;
                int r1 = r0 + 8;
                float sl_s = 0.f, sh_s = 0.f, sl_d = 0.f, sh_d = 0.f;
                #pragma unroll
                for (int nt = 0; nt < 4; nt++) {
                    int col = colBase + wn*32 + nt*8 + t*2;
                    *(__half2*)(Hout + (size_t)r0*CDIM + col) = __floats2half2_rn(acc[mt][nt][0], acc[mt][nt][1]);
                    *(__half2*)(Hout + (size_t)r1*CDIM + col) = __floats2half2_rn(acc[mt][nt][2], acc[mt][nt][3]);
                    sl_s += acc[mt][nt][0]*sa0[nt] + acc[mt][nt][1]*sa1[nt];
                    sh_s += acc[mt][nt][2]*sa0[nt] + acc[mt][nt][3]*sa1[nt];
                    sl_d += acc[mt][nt][0]*sd0[nt] + acc[mt][nt][1]*sd1[nt];
                    sh_d += acc[mt][nt][2]*sd0[nt] + acc[mt][nt][3]*sd1[nt];
                    acc[mt][nt][0] = acc[mt][nt][1] = acc[mt][nt][2] = acc[mt][nt][3] = 0.f;
                }
                sl_s += __shfl_xor_sync(0xffffffffu, sl_s, 1);
                sl_s += __shfl_xor_sync(0xffffffffu, sl_s, 2);
                sh_s += __shfl_xor_sync(0xffffffffu, sh_s, 1);
                sh_s += __shfl_xor_sync(0xffffffffu, sh_s, 2);
                sl_d += __shfl_xor_sync(0xffffffffu, sl_d, 1);
                sl_d += __shfl_xor_sync(0xffffffffu, sl_d, 2);
                sh_d += __shfl_xor_sync(0xffffffffu, sh_d, 1);
                sh_d += __shfl_xor_sync(0xffffffffu, sh_d, 2);
                if (t == 0) {
                    atomicAdd(asb + (size_t)r0*HEADS + hHead, sl_s);
                    atomicAdd(adb + (size_t)r0*HEADS + hHead, sl_d);
                    atomicAdd(asb + (size_t)r1*HEADS + hHead, sh_s);
                    atomicAdd(adb + (size_t)r1*HEADS + hHead, sh_d);
                }
            }
        }
        if (c + 3 < nchunks) issue(c + 3);
    }
}

// ---------------------- softmax-attention aggregation --------------------------
// one warp per node; lane handles 4 consecutive features per 128-feature sweep.
__global__ void agg_kernel(const __half* __restrict__ Hbuf,
                           const float* __restrict__ asv,
                           const float* __restrict__ adv,
                           const float* __restrict__ bias,
                           __half* __restrict__ outH,
                           const float* __restrict__ W2,
                           const float* __restrict__ as2,
                           const float* __restrict__ ad2,
                           int mode) {
    int w = (blockIdx.x * blockDim.x + threadIdx.x) >> 5;
    int lane = threadIdx.x & 31;
    if (w >= NTOT) return;
    int nb[4];
    #pragma unroll
    for (int k = 0; k < 4; k++) nb[k] = d_nbr[w*KNN + k];
    float alpha[4][4];
    #pragma unroll
    for (int h = 0; h < HEADS; h++) {
        float ad = adv[w*HEADS + h];
        float e[4], m = -1e30f;
        #pragma unroll
        for (int k = 0; k < 4; k++) {
            float v = asv[nb[k]*HEADS + h] + ad;
            v = v > 0.f ? v : NEG_SLOPE * v;
            e[k] = v; m = fmaxf(m, v);
        }
        float s = 0.f;
        #pragma unroll
        for (int k = 0; k < 4; k++) { e[k] = __expf(e[k] - m); s += e[k]; }
        float inv = 1.f / s;
        #pragma unroll
        for (int k = 0; k < 4; k++) alpha[k][h] = e[k] * inv;
    }
    float d0 = 0.f, d1 = 0.f;
    #pragma unroll
    for (int grp = 0; grp < 2; grp++) {
        int f = grp*128 + 4*lane;          // 4 consecutive features
        int h = f >> 6;                     // head for this lane's features
        float4 bv = *(const float4*)(bias + f);
        float a0 = bv.x, a1 = bv.y, a2 = bv.z, a3 = bv.w;
        #pragma unroll
        for (int k = 0; k < 4; k++) {
            uint2 hv = *(const uint2*)(Hbuf + (size_t)nb[k]*CDIM + f);
            __half2 q0 = *(__half2*)&hv.x, q1 = *(__half2*)&hv.y;
            float2 f0 = __half22float2(q0), f1 = __half22float2(q1);
            float al = alpha[k][h];
            a0 += al * f0.x; a1 += al * f0.y;
            a2 += al * f1.x; a3 += al * f1.y;
        }
        a0 = a0 > 0.f ? a0 : (__expf(a0) - 1.f);
        a1 = a1 > 0.f ? a1 : (__expf(a1) - 1.f);
        a2 = a2 > 0.f ? a2 : (__expf(a2) - 1.f);
        a3 = a3 > 0.f ? a3 : (__expf(a3) - 1.f);
        if (mode == 0) {
            __half2 o0 = __floats2half2_rn(a0, a1);
            __half2 o1 = __floats2half2_rn(a2, a3);
            uint2 o;
            o.x = *(uint32_t*)&o0; o.y = *(uint32_t*)&o1;
            *(uint2*)(outH + (size_t)w*CDIM + f) = o;
        } else {
            float4 w0 = *(const float4*)(W2 + f*2);       // features f, f+1
            float4 w1 = *(const float4*)(W2 + f*2 + 4);   // features f+2, f+3
            d0 += a0*w0.x + a1*w0.z + a2*w1.x + a3*w1.z;
            d1 += a0*w0.y + a1*w0.w + a2*w1.y + a3*w1.w;
        }
    }
    if (mode == 1) {
        #pragma unroll
        for (int off = 16; off > 0; off >>= 1) {
            d0 += __shfl_xor_sync(0xffffffffu, d0, off);
            d1 += __shfl_xor_sync(0xffffffffu, d1, off);
        }
        if (lane == 0) {
            d_h2[w*2]   = d0;
            d_h2[w*2+1] = d1;
            d_a2s[w] = d0*as2[0] + d1*as2[1];
            d_a2d[w] = d0*ad2[0] + d1*ad2[1];
        }
    }
}

__global__ void final_kernel(const float* __restrict__ b2, float* __restrict__ out) {
    int n = blockIdx.x * blockDim.x + threadIdx.x;
    if (n >= NTOT) return;
    int nb[4];
    #pragma unroll
    for (int k = 0; k < 4; k++) nb[k] = d_nbr[n*KNN + k];
    float ad = d_a2d[n];
    float e[4], m = -1e30f;
    #pragma unroll
    for (int k = 0; k < 4; k++) {
        float v = d_a2s[nb[k]] + ad;
        v = v > 0.f ? v : NEG_SLOPE * v;
        e[k] = v; m = fmaxf(m, v);
    }
    float s = 0.f;
    #pragma unroll
    for (int k = 0; k < 4; k++) { e[k] = __expf(e[k] - m); s += e[k]; }
    float inv = 1.f / s;
    float o0 = 0.f, o1 = 0.f;
    #pragma unroll
    for (int k = 0; k < 4; k++) {
        float a = e[k] * inv;
        o0 += a * d_h2[nb[k]*2];
        o1 += a * d_h2[nb[k]*2 + 1];
    }
    int orig = ((n >> 13) << 13) + d_sorted[n];
    out[orig*2]     = o0 + b2[0];
    out[orig*2 + 1] = o1 + b2[1];
}

// --------------------------------- launch --------------------------------------
extern "C" void kernel_launch(void* const* d_in, const int* in_sizes, int n_in,
                              void* d_out, int out_size) {
    const float* coords   = (const float*)d_in[0];
    const float* x        = (const float*)d_in[1];
    const float* W0       = (const float*)d_in[2];
    const float* att_src0 = (const float*)d_in[3];
    const float* att_dst0 = (const float*)d_in[4];
    const float* b0       = (const float*)d_in[5];
    const float* W1       = (const float*)d_in[6];
    const float* att_src1 = (const float*)d_in[7];
    const float* att_dst1 = (const float*)d_in[8];
    const float* b1       = (const float*)d_in[9];
    const float* W2       = (const float*)d_in[10];
    const float* att_src2 = (const float*)d_in[11];
    const float* att_dst2 = (const float*)d_in[12];
    const float* b2       = (const float*)d_in[13];
    float* out = (float*)d_out;

    float *asp, *adp;
    __half *ahp, *hhp;
    uint32_t *wp0, *wp1;
    cudaGetSymbolAddress((void**)&hhp, d_hh);
    cudaGetSymbolAddress((void**)&ahp, d_ah);
    cudaGetSymbolAddress((void**)&asp, d_as);
    cudaGetSymbolAddress((void**)&adp, d_ad);
    cudaGetSymbolAddress((void**)&wp0, d_wp0);
    cudaGetSymbolAddress((void**)&wp1, d_wp1);

    cudaFuncSetAttribute(gemm_f16_kernel, cudaFuncAttributeMaxDynamicSharedMemorySize, GEMM_SMEM);

    // fused prep: zero counters + att scalars, pack both W (k-major)
    prep_kernel<<<(2*NTOT*HEADS + 255)/256, 256>>>(W0, W1, wp0, wp1);
    count_kernel<<<512, 256>>>(coords);
    scan_kernel<<<BATCH, 1024>>>();
    scatter_kernel<<<512, 256>>>(coords);

    // fused: kNN search + permute/convert run concurrently
    knn_perm_kernel<<<KNN_BLOCKS + PERM_BLOCKS, 256>>>(x, ahp);

    dim3 ggrid(148, 2);
    float* as0 = asp;               float* ad0 = adp;
    float* as1 = asp + NTOT*HEADS;  float* ad1 = adp + NTOT*HEADS;

    // Layer 0
    gemm_f16_kernel<<<ggrid, 256, GEMM_SMEM>>>(ahp, wp0, att_src0, att_dst0, hhp, as0, ad0);
    agg_kernel<<<NTOT/8, 256>>>(hhp, as0, ad0, b0, ahp, nullptr, nullptr, nullptr, 0);

    // Layer 1 (+ fused layer-2 projection)
    gemm_f16_kernel<<<ggrid, 256, GEMM_SMEM>>>(ahp, wp1, att_src1, att_dst1, hhp, as1, ad1);
    agg_kernel<<<NTOT/8, 256>>>(hhp, as1, ad1, b1, nullptr, W2, att_src2, att_dst2, 1);

    // Final attention layer
    final_kernel<<<512, 256>>>(b2, out);
}

// round 17
// speedup vs baseline: 1.0485x; 1.0485x over previous
#include <cuda_runtime.h>
#include <cuda_fp16.h>
#include <cstdint>
#include <math.h>

#define BATCH 16
#define PP    8192
#define NTOT  (BATCH*PP)     // 131072
#define KNN   4
#define CDIM  256
#define HEADS 4
#define FDIM  64
#define GRID  64
#define NCELL (GRID*GRID)    // 4096
#define NEG_SLOPE 0.2f

// ------------------- scratch (__device__ globals, no mallocs) -------------------
__device__ int      d_cnt[BATCH*NCELL];
__device__ int      d_start[BATCH*(NCELL+1)];
__device__ int      d_cur[BATCH*NCELL];
__device__ int      d_sorted[NTOT];
__device__ float2   d_sc[NTOT];
__device__ int      d_nbr[NTOT*KNN];
__device__ __half   d_hh[NTOT*CDIM];       // GEMM output (fp16, sorted space)
__device__ __half   d_ah[NTOT*CDIM];       // fp16 GEMM input
__device__ float    d_as[2*NTOT*HEADS];    // att scalars, per-layer halves
__device__ float    d_ad[2*NTOT*HEADS];
__device__ float    d_h2[NTOT*2];
__device__ float    d_a2s[NTOT];
__device__ float    d_a2d[NTOT];
__device__ uint32_t d_wp0[256*128];        // W packed k-major: [n][k2] half2
__device__ uint32_t d_wp1[256*128];

// ----------------------------- PTX helpers --------------------------------------
__device__ __forceinline__ uint32_t smem_u32(const void* p) {
    uint32_t a;
    asm("{ .reg .u64 t; cvta.to.shared.u64 t, %1; cvt.u32.u64 %0, t; }" : "=r"(a) : "l"(p));
    return a;
}
__device__ __forceinline__ void cp16(uint32_t dst, const void* src) {
    asm volatile("cp.async.cg.shared.global [%0], [%1], 16;" :: "r"(dst), "l"(src));
}
#define CP_COMMIT() asm volatile("cp.async.commit_group;" ::: "memory")
#define CP_WAIT(N)  asm volatile("cp.async.wait_group %0;" :: "n"(N) : "memory")

__device__ __forceinline__ void mma_f16(float d[4], const uint32_t a[4], const uint32_t b[2]) {
    asm volatile(
        "mma.sync.aligned.m16n8k16.row.col.f32.f16.f16.f32 "
        "{%0,%1,%2,%3}, {%4,%5,%6,%7}, {%8,%9}, {%0,%1,%2,%3};"
        : "+f"(d[0]), "+f"(d[1]), "+f"(d[2]), "+f"(d[3])
        : "r"(a[0]), "r"(a[1]), "r"(a[2]), "r"(a[3]), "r"(b[0]), "r"(b[1]));
}
__device__ __forceinline__ void ldsm_x4(uint32_t r[4], uint32_t addr) {
    asm volatile("ldmatrix.sync.aligned.m8n8.x4.shared.b16 {%0,%1,%2,%3}, [%4];"
        : "=r"(r[0]), "=r"(r[1]), "=r"(r[2]), "=r"(r[3]) : "r"(addr));
}

// -------------- prep: zero counters/att-scalars + pack both W (fused) ----------
__global__ void prep_kernel(const float* __restrict__ W0, const float* __restrict__ W1,
                            uint32_t* __restrict__ Wp0, uint32_t* __restrict__ Wp1) {
    int i = blockIdx.x * blockDim.x + threadIdx.x;
    if (i < BATCH*NCELL) d_cnt[i] = 0;
    if (i < 2*NTOT*HEADS) { d_as[i] = 0.f; d_ad[i] = 0.f; }
    if (i < 256*128) {
        int n = i >> 7, k2 = i & 127;
        __half2 v0 = __floats2half2_rn(W0[(2*k2)*CDIM + n], W0[(2*k2+1)*CDIM + n]);
        __half2 v1 = __floats2half2_rn(W1[(2*k2)*CDIM + n], W1[(2*k2+1)*CDIM + n]);
        Wp0[i] = *(uint32_t*)&v0;
        Wp1[i] = *(uint32_t*)&v1;
    }
}

// ------------------------------- kNN pipeline ----------------------------------
__device__ __forceinline__ int cell_of(float v) {
    int c = (int)(v * GRID);
    return min(GRID-1, max(0, c));
}
__global__ void count_kernel(const float* __restrict__ coords) {
    int i = blockIdx.x * blockDim.x + threadIdx.x;
    if (i >= NTOT) return;
    float2 c = ((const float2*)coords)[i];
    int b = i >> 13;
    atomicAdd(&d_cnt[b*NCELL + cell_of(c.y)*GRID + cell_of(c.x)], 1);
}
// NCELL=4096, 1024 threads: per-thread 4-cell sums + shuffle-based block scan.
__global__ void scan_kernel() {
    __shared__ int s[32];
    int b = blockIdx.x, t = threadIdx.x;
    int lane = t & 31, wrp = t >> 5;
    int base = b*NCELL + t*4;
    int v0 = d_cnt[base], v1 = d_cnt[base+1], v2 = d_cnt[base+2], v3 = d_cnt[base+3];
    int p0 = v0, p1 = p0 + v1, p2 = p1 + v2, p3 = p2 + v3;
    int w = p3;
    #pragma unroll
    for (int off = 1; off < 32; off <<= 1) {
        int n = __shfl_up_sync(0xffffffffu, w, off);
        if (lane >= off) w += n;
    }
    if (lane == 31) s[wrp] = w;
    __syncthreads();
    if (wrp == 0) {
        int v = s[lane];
        #pragma unroll
        for (int off = 1; off < 32; off <<= 1) {
            int n = __shfl_up_sync(0xffffffffu, v, off);
            if (lane >= off) v += n;
        }
        s[lane] = v;
    }
    __syncthreads();
    int warpbase = (wrp > 0) ? s[wrp-1] : 0;
    int incl = warpbase + w;
    int gbase = incl - p3;
    int o = b*(NCELL+1) + t*4;
    d_start[o]   = gbase;
    d_start[o+1] = gbase + p0;
    d_start[o+2] = gbase + p1;
    d_start[o+3] = gbase + p2;
    int c = b*NCELL + t*4;
    d_cur[c]   = gbase;
    d_cur[c+1] = gbase + p0;
    d_cur[c+2] = gbase + p1;
    d_cur[c+3] = gbase + p2;
    if (t == 1023) d_start[b*(NCELL+1) + NCELL] = incl;
}
__global__ void scatter_kernel(const float* __restrict__ coords) {
    int i = blockIdx.x * blockDim.x + threadIdx.x;
    if (i >= NTOT) return;
    float2 c = ((const float2*)coords)[i];
    int b = i >> 13, p = i & (PP-1);
    int cell = cell_of(c.y)*GRID + cell_of(c.x);
    int pos = atomicAdd(&d_cur[b*NCELL + cell], 1);
    d_sorted[b*PP + pos] = p;
    d_sc[b*PP + pos] = c;
}

__device__ __forceinline__ void ins4(float d2, int gi, float bd[4], int bi[4]) {
    if (d2 < bd[3]) {
        if (d2 < bd[2]) { bd[3]=bd[2]; bi[3]=bi[2];
            if (d2 < bd[1]) { bd[2]=bd[1]; bi[2]=bi[1];
                if (d2 < bd[0]) { bd[1]=bd[0]; bi[1]=bi[0]; bd[0]=d2; bi[0]=gi; }
                else            { bd[1]=d2; bi[1]=gi; }
            } else { bd[2]=d2; bi[2]=gi; }
        } else { bd[3]=d2; bi[3]=gi; }
    }
}
__device__ __forceinline__ void scan_cell(int b, int cell, float qx, float qy,
                                          float bd[4], int bi[4]) {
    int s0 = d_start[b*(NCELL+1) + cell];
    int s1 = d_start[b*(NCELL+1) + cell + 1];
    int base = b << 13;
    for (int j = s0; j < s1; j++) {
        float2 c2 = d_sc[base + j];
        float dx = c2.x - qx, dy = c2.y - qy;
        ins4(dx*dx + dy*dy, base + j, bd, bi);
    }
}

__device__ __forceinline__ void knn_work(int n) {
    int b = n >> 13;
    float2 q = d_sc[n];
    int cx = cell_of(q.x), cy = cell_of(q.y);
    float bd[4] = {1e30f, 1e30f, 1e30f, 1e30f};
    int   bi[4] = {n, n, n, n};
    int x0 = max(0, cx-1), x1 = min(GRID-1, cx+1);
    int y0 = max(0, cy-1), y1 = min(GRID-1, cy+1);
    for (int yy = y0; yy <= y1; yy++) {
        int s0 = d_start[b*(NCELL+1) + yy*GRID + x0];
        int s1 = d_start[b*(NCELL+1) + yy*GRID + x1 + 1];
        int base = b << 13;
        for (int j = s0; j < s1; j++) {
            float2 c2 = d_sc[base + j];
            float dx = c2.x - q.x, dy = c2.y - q.y;
            ins4(dx*dx + dy*dy, base + j, bd, bi);
        }
    }
    const float hcell = 1.0f / GRID;
    int r = 1;
    while (true) {
        float bound = r * hcell;
        if (bd[3] <= bound*bound) break;
        bool full = (cx-r <= 0) && (cy-r <= 0) && (cx+r >= GRID-1) && (cy+r >= GRID-1);
        if (full) break;
        r++;
        int rx0 = cx-r, rx1 = cx+r, ry0 = cy-r, ry1 = cy+r;
        int cxl = max(0, rx0), cxr = min(GRID-1, rx1);
        if (ry0 >= 0) {
            int s0 = d_start[b*(NCELL+1) + ry0*GRID + cxl];
            int s1 = d_start[b*(NCELL+1) + ry0*GRID + cxr + 1];
            int base = b << 13;
            for (int j = s0; j < s1; j++) {
                float2 c2 = d_sc[base + j];
                float dx = c2.x - q.x, dy = c2.y - q.y;
                ins4(dx*dx + dy*dy, base + j, bd, bi);
            }
        }
        if (ry1 <= GRID-1) {
            int s0 = d_start[b*(NCELL+1) + ry1*GRID + cxl];
            int s1 = d_start[b*(NCELL+1) + ry1*GRID + cxr + 1];
            int base = b << 13;
            for (int j = s0; j < s1; j++) {
                float2 c2 = d_sc[base + j];
                float dx = c2.x - q.x, dy = c2.y - q.y;
                ins4(dx*dx + dy*dy, base + j, bd, bi);
            }
        }
        int cyl = max(0, ry0+1), cyr = min(GRID-1, ry1-1);
        if (rx0 >= 0)      for (int yy = cyl; yy <= cyr; yy++) scan_cell(b, yy*GRID + rx0, q.x, q.y, bd, bi);
        if (rx1 <= GRID-1) for (int yy = cyl; yy <= cyr; yy++) scan_cell(b, yy*GRID + rx1, q.x, q.y, bd, bi);
    }
    #pragma unroll
    for (int k = 0; k < KNN; k++) d_nbr[n*KNN + k] = bi[k];
}

// -------- fused: blocks [0,512) do kNN; blocks [512, 512+16384) do permute -----
#define KNN_BLOCKS 512
#define PERM_BLOCKS (NTOT/8)

__global__ void knn_perm_kernel(const float* __restrict__ x, __half* __restrict__ xp) {
    if (blockIdx.x < KNN_BLOCKS) {
        int n = blockIdx.x * blockDim.x + threadIdx.x;
        if (n < NTOT) knn_work(n);
    } else {
        int w = ((blockIdx.x - KNN_BLOCKS) * blockDim.x + threadIdx.x) >> 5;
        int lane = threadIdx.x & 31;
        if (w >= NTOT) return;
        int orig = ((w >> 13) << 13) + d_sorted[w];
        const float4* src = (const float4*)(x + (size_t)orig*CDIM);
        float4 v0 = src[lane*2], v1 = src[lane*2 + 1];
        __half2 h0 = __floats2half2_rn(v0.x, v0.y);
        __half2 h1 = __floats2half2_rn(v0.z, v0.w);
        __half2 h2 = __floats2half2_rn(v1.x, v1.y);
        __half2 h3 = __floats2half2_rn(v1.z, v1.w);
        uint4 o;
        o.x = *(uint32_t*)&h0; o.y = *(uint32_t*)&h1;
        o.z = *(uint32_t*)&h2; o.w = *(uint32_t*)&h3;
        *(uint4*)(xp + (size_t)w*CDIM + lane*8) = o;
    }
}

// --------------- fp16 persistent-W GEMM + fused attention scalars --------------
// 4-deep A pipeline, ONE __syncthreads per chunk, ldmatrix for A AND B fragments.
#define NS2K 132                       // W smem row stride (u32): 128 k2 + 4 pad
#define AS2 20
#define W_SMEM_U32 (128*NS2K)          // 16896 u32 (128 n-rows per CTA half)
#define A_SMEM_H2 (128*AS2)            // 2560 u32
#define NBUF 4
#define GEMM_SMEM ((W_SMEM_U32 + NBUF*A_SMEM_H2)*4)   // 108544 bytes

__global__ void __launch_bounds__(256, 2) gemm_f16_kernel(
    const __half* __restrict__ A, const uint32_t* __restrict__ Wp,
    const float* __restrict__ asrc, const float* __restrict__ adst,
    __half* __restrict__ Hout, float* __restrict__ asb, float* __restrict__ adb)
{
    extern __shared__ uint32_t sm2[];
    uint32_t sbase = smem_u32(sm2);
    uint32_t abase = sbase + W_SMEM_U32*4;

    int tid = threadIdx.x;
    int wid = tid >> 5, lane = tid & 31;
    int g = lane >> 2, t = lane & 3;
    int wm = wid & 1, wn = wid >> 1;
    int cHalf = blockIdx.y;
    int colBase = cHalf*128;

    // stage W half (128 n-rows x 128 k2) into smem, k-major rows
    for (int i = tid; i < 128*32; i += 256) {
        int nl = i >> 5, k4 = i & 31;
        cp16(sbase + (uint32_t)(nl*NS2K + k4*4)*4, Wp + (size_t)(colBase + nl)*128 + k4*4);
    }
    CP_COMMIT();

    float sa0[4], sa1[4], sd0[4], sd1[4];
    #pragma unroll
    for (int nt = 0; nt < 4; nt++) {
        int col = colBase + wn*32 + nt*8 + t*2;
        sa0[nt] = asrc[col]; sa1[nt] = asrc[col+1];
        sd0[nt] = adst[col]; sd1[nt] = adst[col+1];
    }
    int hHead = (colBase + wn*32) >> 6;

    int ntiles = (1024 - blockIdx.x + 147) / 148;
    int nchunks = ntiles * 8;

    auto issue = [&](int c) {
        int rt = blockIdx.x + (c >> 3)*148;
        int kk = c & 7;
        const __half* src = A + (size_t)rt*128*CDIM + kk*32;
        uint32_t dstb = abase + (uint32_t)(c & (NBUF-1))*A_SMEM_H2*4;
        #pragma unroll
        for (int i = 0; i < 2; i++) {
            int idx = tid + i*256;
            int r = idx >> 2, c4 = idx & 3;
            cp16(dstb + (uint32_t)(r*AS2 + c4*4)*4, src + (size_t)r*CDIM + c4*8);
        }
        CP_COMMIT();
    };

    float acc[4][4][4];
    #pragma unroll
    for (int mt = 0; mt < 4; mt++)
        #pragma unroll
        for (int nt = 0; nt < 4; nt++)
            #pragma unroll
            for (int i = 0; i < 4; i++) acc[mt][nt][i] = 0.f;

    issue(0);
    if (nchunks > 1) issue(1);
    if (nchunks > 2) issue(2);

    // A ldmatrix per-lane offset (u32): lanes 0-15 rows 0-15 @k 0; 16-31 @ +4
    uint32_t lrowA = (uint32_t)((wm*64 + (lane & 15))*AS2 + (lane >> 4)*4);
    // B ldmatrix per-lane offsets (u32): 4 matrices = (nt, khalf) pairs
    int mi = lane >> 3, brow = lane & 7;
    int ntA = mi >> 1, khf = mi & 1;
    uint32_t lB0 = (uint32_t)((wn*32 + ntA*8     + brow)*NS2K + khf*4);   // nt 0,1
    uint32_t lB1 = (uint32_t)((wn*32 + (ntA+2)*8 + brow)*NS2K + khf*4);   // nt 2,3

    #pragma unroll 1
    for (int c = 0; c < nchunks; c++) {
        int d = nchunks - 1 - c;
        if (d >= 2)      { CP_WAIT(2); }
        else if (d == 1) { CP_WAIT(1); }
        else             { CP_WAIT(0); }
        __syncthreads();     // all warps done with chunk c-1; buffer (c+3)%4 free
        int kk = c & 7;
        uint32_t abuf_b = abase + (uint32_t)(c & (NBUF-1))*A_SMEM_H2*4;
        #pragma unroll
        for (int ks = 0; ks < 2; ks++) {
            int kh = ks*8;
            uint32_t koff = (uint32_t)(kk*16 + kh);
            uint32_t af[4][4], b01[4], b23[4];
            #pragma unroll
            for (int mt = 0; mt < 4; mt++)
                ldsm_x4(af[mt], abuf_b + (lrowA + (uint32_t)(mt*16*AS2 + kh))*4);
            ldsm_x4(b01, sbase + (lB0 + koff)*4);
            ldsm_x4(b23, sbase + (lB1 + koff)*4);
            #pragma unroll
            for (int mt = 0; mt < 4; mt++) {
                #pragma unroll
                for (int nt = 0; nt < 4; nt++) {
                    const uint32_t* bb = (nt < 2) ? &b01[nt*2] : &b23[(nt-2)*2];
                    mma_f16(acc[mt][nt], af[mt], bb);
                }
            }
        }
        if (kk == 7) {
            int rt = blockIdx.x + (c >> 3)*148;
            int rowBase = rt*128;
            #pragma unroll
            for (int mt = 0; mt < 4; mt++) {
                int r0 = rowBase + wm*64 + mt*16 + g;
                int r1 = r0 + 8;
                float sl_s = 0.f, sh_s = 0.f, sl_d = 0.f, sh_d = 0.f;
                #pragma unroll
                for (int nt = 0; nt < 4; nt++) {
                    int col = colBase + wn*32 + nt*8 + t*2;
                    *(__half2*)(Hout + (size_t)r0*CDIM + col) = __floats2half2_rn(acc[mt][nt][0], acc[mt][nt][1]);
                    *(__half2*)(Hout + (size_t)r1*CDIM + col) = __floats2half2_rn(acc[mt][nt][2], acc[mt][nt][3]);
                    sl_s += acc[mt][nt][0]*sa0[nt] + acc[mt][nt][1]*sa1[nt];
                    sh_s += acc[mt][nt][2]*sa0[nt] + acc[mt][nt][3]*sa1[nt];
                    sl_d += acc[mt][nt][0]*sd0[nt] + acc[mt][nt][1]*sd1[nt];
                    sh_d += acc[mt][nt][2]*sd0[nt] + acc[mt][nt][3]*sd1[nt];
                    acc[mt][nt][0] = acc[mt][nt][1] = acc[mt][nt][2] = acc[mt][nt][3] = 0.f;
                }
                sl_s += __shfl_xor_sync(0xffffffffu, sl_s, 1);
                sl_s += __shfl_xor_sync(0xffffffffu, sl_s, 2);
                sh_s += __shfl_xor_sync(0xffffffffu, sh_s, 1);
                sh_s += __shfl_xor_sync(0xffffffffu, sh_s, 2);
                sl_d += __shfl_xor_sync(0xffffffffu, sl_d, 1);
                sl_d += __shfl_xor_sync(0xffffffffu, sl_d, 2);
                sh_d += __shfl_xor_sync(0xffffffffu, sh_d, 1);
                sh_d += __shfl_xor_sync(0xffffffffu, sh_d, 2);
                if (t == 0) {
                    atomicAdd(asb + (size_t)r0*HEADS + hHead, sl_s);
                    atomicAdd(adb + (size_t)r0*HEADS + hHead, sl_d);
                    atomicAdd(asb + (size_t)r1*HEADS + hHead, sh_s);
                    atomicAdd(adb + (size_t)r1*HEADS + hHead, sh_d);
                }
            }
        }
        if (c + 3 < nchunks) issue(c + 3);
    }
}

// ---------------------- softmax-attention aggregation --------------------------
__global__ void agg_kernel(const __half* __restrict__ Hbuf,
                           const float* __restrict__ asv,
                           const float* __restrict__ adv,
                           const float* __restrict__ bias,
                           __half* __restrict__ outH,
                           const float* __restrict__ W2,
                           const float* __restrict__ as2,
                           const float* __restrict__ ad2,
                           int mode) {
    int w = (blockIdx.x * blockDim.x + threadIdx.x) >> 5;
    int lane = threadIdx.x & 31;
    if (w >= NTOT) return;
    int nb[4];
    #pragma unroll
    for (int k = 0; k < 4; k++) nb[k] = d_nbr[w*KNN + k];
    float alpha[4][4];
    #pragma unroll
    for (int h = 0; h < HEADS; h++) {
        float ad = adv[w*HEADS + h];
        float e[4], m = -1e30f;
        #pragma unroll
        for (int k = 0; k < 4; k++) {
            float v = asv[nb[k]*HEADS + h] + ad;
            v = v > 0.f ? v : NEG_SLOPE * v;
            e[k] = v; m = fmaxf(m, v);
        }
        float s = 0.f;
        #pragma unroll
        for (int k = 0; k < 4; k++) { e[k] = __expf(e[k] - m); s += e[k]; }
        float inv = 1.f / s;
        #pragma unroll
        for (int k = 0; k < 4; k++) alpha[k][h] = e[k] * inv;
    }
    float d0 = 0.f, d1 = 0.f;
    #pragma unroll
    for (int h = 0; h < HEADS; h++) {
        int f = h*FDIM + 2*lane;
        float ax = bias[f], ay = bias[f+1];
        #pragma unroll
        for (int k = 0; k < 4; k++) {
            __half2 hv = *(const __half2*)(Hbuf + (size_t)nb[k]*CDIM + f);
            float2 fv = __half22float2(hv);
            ax += alpha[k][h] * fv.x;
            ay += alpha[k][h] * fv.y;
        }
        ax = ax > 0.f ? ax : (__expf(ax) - 1.f);
        ay = ay > 0.f ? ay : (__expf(ay) - 1.f);
        if (mode == 0) {
            *(__half2*)(outH + (size_t)w*CDIM + f) = __floats2half2_rn(ax, ay);
        } else {
            float4 wv = *(const float4*)(W2 + f*2);
            d0 += ax*wv.x + ay*wv.z;
            d1 += ax*wv.y + ay*wv.w;
        }
    }
    if (mode == 1) {
        #pragma unroll
        for (int off = 16; off > 0; off >>= 1) {
            d0 += __shfl_xor_sync(0xffffffffu, d0, off);
            d1 += __shfl_xor_sync(0xffffffffu, d1, off);
        }
        if (lane == 0) {
            d_h2[w*2]   = d0;
            d_h2[w*2+1] = d1;
            d_a2s[w] = d0*as2[0] + d1*as2[1];
            d_a2d[w] = d0*ad2[0] + d1*ad2[1];
        }
    }
}

__global__ void final_kernel(const float* __restrict__ b2, float* __restrict__ out) {
    int n = blockIdx.x * blockDim.x + threadIdx.x;
    if (n >= NTOT) return;
    int nb[4];
    #pragma unroll
    for (int k = 0; k < 4; k++) nb[k] = d_nbr[n*KNN + k];
    float ad = d_a2d[n];
    float e[4], m = -1e30f;
    #pragma unroll
    for (int k = 0; k < 4; k++) {
        float v = d_a2s[nb[k]] + ad;
        v = v > 0.f ? v : NEG_SLOPE * v;
        e[k] = v; m = fmaxf(m, v);
    }
    float s = 0.f;
    #pragma unroll
    for (int k = 0; k < 4; k++) { e[k] = __expf(e[k] - m); s += e[k]; }
    float inv = 1.f / s;
    float o0 = 0.f, o1 = 0.f;
    #pragma unroll
    for (int k = 0; k < 4; k++) {
        float a = e[k] * inv;
        o0 += a * d_h2[nb[k]*2];
        o1 += a * d_h2[nb[k]*2 + 1];
    }
    int orig = ((n >> 13) << 13) + d_sorted[n];
    out[orig*2]     = o0 + b2[0];
    out[orig*2 + 1] = o1 + b2[1];
}

// --------------------------------- launch --------------------------------------
extern "C" void kernel_launch(void* const* d_in, const int* in_sizes, int n_in,
                              void* d_out, int out_size) {
    const float* coords   = (const float*)d_in[0];
    const float* x        = (const float*)d_in[1];
    const float* W0       = (const float*)d_in[2];
    const float* att_src0 = (const float*)d_in[3];
    const float* att_dst0 = (const float*)d_in[4];
    const float* b0       = (const float*)d_in[5];
    const float* W1       = (const float*)d_in[6];
    const float* att_src1 = (const float*)d_in[7];
    const float* att_dst1 = (const float*)d_in[8];
    const float* b1       = (const float*)d_in[9];
    const float* W2       = (const float*)d_in[10];
    const float* att_src2 = (const float*)d_in[11];
    const float* att_dst2 = (const float*)d_in[12];
    const float* b2       = (const float*)d_in[13];
    float* out = (float*)d_out;

    float *asp, *adp;
    __half *ahp, *hhp;
    uint32_t *wp0, *wp1;
    cudaGetSymbolAddress((void**)&hhp, d_hh);
    cudaGetSymbolAddress((void**)&ahp, d_ah);
    cudaGetSymbolAddress((void**)&asp, d_as);
    cudaGetSymbolAddress((void**)&adp, d_ad);
    cudaGetSymbolAddress((void**)&wp0, d_wp0);
    cudaGetSymbolAddress((void**)&wp1, d_wp1);

    cudaFuncSetAttribute(gemm_f16_kernel, cudaFuncAttributeMaxDynamicSharedMemorySize, GEMM_SMEM);

    // fused prep: zero counters + att scalars, pack both W (k-major)
    prep_kernel<<<(2*NTOT*HEADS + 255)/256, 256>>>(W0, W1, wp0, wp1);
    count_kernel<<<512, 256>>>(coords);
    scan_kernel<<<BATCH, 1024>>>();
    scatter_kernel<<<512, 256>>>(coords);

    // fused: kNN search + permute/convert run concurrently
    knn_perm_kernel<<<KNN_BLOCKS + PERM_BLOCKS, 256>>>(x, ahp);

    dim3 ggrid(148, 2);
    float* as0 = asp;               float* ad0 = adp;
    float* as1 = asp + NTOT*HEADS;  float* ad1 = adp + NTOT*HEADS;

    // Layer 0
    gemm_f16_kernel<<<ggrid, 256, GEMM_SMEM>>>(ahp, wp0, att_src0, att_dst0, hhp, as0, ad0);
    agg_kernel<<<NTOT/8, 256>>>(hhp, as0, ad0, b0, ahp, nullptr, nullptr, nullptr, 0);

    // Layer 1 (+ fused layer-2 projection)
    gemm_f16_kernel<<<ggrid, 256, GEMM_SMEM>>>(ahp, wp1, att_src1, att_dst1, hhp, as1, ad1);
    agg_kernel<<<NTOT/8, 256>>>(hhp, as1, ad1, b1, nullptr, W2, att_src2, att_dst2, 1);

    // Final attention layer
    final_kernel<<<512, 256>>>(b2, out);
}